// round 15
// baseline (speedup 1.0000x reference)
#include <cuda_runtime.h>
#include <cuda_bf16.h>
#include <cstdint>

// ============================================================
// OpticalConvolution: 3x3 conv pad1 NCHW fp32 as implicit GEMM
//   M=Cout=256, N=B*H*W=50176, K=Cin*9=1152
// bf16 3-term split (AhiBhi + AhiBlo + AloBhi) on mma.sync
// (m16n8k16, fp32 accum).
// R13: BN=128->64, smem 131KB->96KB => 2 CTAs/SM (16 warps)
// to fix the measured latency starvation (~23 cyc/HMMA eff).
// ============================================================

constexpr int Cin  = 128;
constexpr int H    = 56;
constexpr int W    = 56;
constexpr int Cout = 256;
constexpr int Bsz  = 16;
constexpr int NPIX = H * W;          // 3136
constexpr int NTOT = Bsz * NPIX;     // 50176
constexpr int KK   = Cin * 9;        // 1152

constexpr int BM = 128;
constexpr int BN = 64;
constexpr int KC = 64;               // K per chunk (one tap, 64 cins)
constexpr int NCHUNK = KK / KC;      // 18

constexpr int TILE_A = BM * 128;     // 16384 B (128 rows x 128B)
constexpr int TILE_B = BN * 128;     // 8192 B
constexpr int STAGE  = 2 * TILE_A + 2 * TILE_B;   // 49152
constexpr int SMEM_TOTAL = 2 * STAGE;             // 98304 -> 2 CTAs/SM

// stage-relative offsets
constexpr int OFF_AHI = 0;
constexpr int OFF_ALO = TILE_A;
constexpr int OFF_BHI = 2 * TILE_A;
constexpr int OFF_BLO = 2 * TILE_A + TILE_B;

// ---- device scratch ----
__device__ __align__(16) __nv_bfloat16 g_in_hi[(size_t)NTOT * Cin];
__device__ __align__(16) __nv_bfloat16 g_in_lo[(size_t)NTOT * Cin];
__device__ __align__(16) __nv_bfloat16 g_w_hi[Cout * KK];
__device__ __align__(16) __nv_bfloat16 g_w_lo[Cout * KK];

// ============================================================
// helpers
// ============================================================
__device__ __forceinline__ uint32_t smem_u32(const void* p) {
    uint32_t a;
    asm("{ .reg .u64 t; cvta.to.shared.u64 t, %1; cvt.u32.u64 %0, t; }"
        : "=r"(a) : "l"(p));
    return a;
}

__device__ __forceinline__ void cp16(uint32_t dst, const void* src, uint32_t srcsize) {
    asm volatile("cp.async.cg.shared.global [%0], [%1], 16, %2;"
                 :: "r"(dst), "l"(src), "r"(srcsize) : "memory");
}
#define CP_COMMIT() asm volatile("cp.async.commit_group;" ::: "memory")
#define CP_WAIT1()  asm volatile("cp.async.wait_group 1;" ::: "memory")
#define CP_WAIT0()  asm volatile("cp.async.wait_group 0;" ::: "memory")

#define LDSM_X4(r0, r1, r2, r3, addr) \
    asm volatile("ldmatrix.sync.aligned.m8n8.x4.shared.b16 {%0,%1,%2,%3}, [%4];" \
                 : "=r"(r0), "=r"(r1), "=r"(r2), "=r"(r3) : "r"(addr))

#define MMA_BF16(d, a, b0, b1) \
    asm volatile("mma.sync.aligned.m16n8k16.row.col.f32.bf16.bf16.f32 " \
                 "{%0,%1,%2,%3}, {%4,%5,%6,%7}, {%8,%9}, {%0,%1,%2,%3};" \
                 : "+f"((d)[0]), "+f"((d)[1]), "+f"((d)[2]), "+f"((d)[3]) \
                 : "r"((a)[0]), "r"((a)[1]), "r"((a)[2]), "r"((a)[3]), \
                   "r"(b0), "r"(b1))

// ============================================================
// Prep kernels (unchanged from R13 pass)
// ============================================================
__global__ __launch_bounds__(224)
void prep_input_kernel(const float* __restrict__ in) {
    __shared__ float stage[W][33];
    const int b = blockIdx.y, y = blockIdx.x;
    const int t = threadIdx.x;           // 0..223
    const int xg = t % 56;
    const int cg = t / 56;               // 0..3
    for (int cin0 = 0; cin0 < Cin; cin0 += 32) {
#pragma unroll
        for (int j = 0; j < 8; ++j) {
            int cl = j * 4 + cg;
            stage[xg][cl] = in[((size_t)(b * Cin + cin0 + cl) * H + y) * W + xg];
        }
        __syncthreads();
#pragma unroll
        for (int j = 0; j < 8; ++j) {
            int o = t + 224 * j;          // 0..1791
            int cl = o & 31;
            int x  = o >> 5;
            float v = stage[x][cl];
            __nv_bfloat16 hi = __float2bfloat16(v);
            float lov = v - __bfloat162float(hi);
            size_t oi = ((size_t)b * NPIX + (size_t)y * W + x) * Cin + cin0 + cl;
            g_in_hi[oi] = hi;
            g_in_lo[oi] = __float2bfloat16(lov);
        }
        __syncthreads();
    }
}

__global__ __launch_bounds__(256)
void prep_weights_kernel(const float* __restrict__ w) {
    int o = blockIdx.x * 256 + threadIdx.x;
    if (o >= Cout * KK) return;
    int cout = o / KK;
    int k    = o - cout * KK;
    int r    = k >> 7;           // tap 0..8
    int cin  = k & 127;
    float v = w[((size_t)cout * Cin + cin) * 9 + r];
    __nv_bfloat16 hi = __float2bfloat16(v);
    g_w_hi[o] = hi;
    g_w_lo[o] = __float2bfloat16(v - __bfloat162float(hi));
}

// ============================================================
// Main mma.sync kernel: BM=128 x BN=64, 2 CTAs/SM
// ============================================================
__global__ __launch_bounds__(256, 2)
void conv_mma_kernel(const float* __restrict__ bias, float* __restrict__ out) {
    extern __shared__ char smem[];
    const uint32_t sb = smem_u32(smem);
    const int tid = threadIdx.x;
    const int wid = tid >> 5;
    const int lid = tid & 31;
    const int warpM = wid >> 2;       // 0..1 -> 64 cout rows each
    const int warpN = wid & 3;        // 0..3 -> 16 pixel cols each

    const int n0  = blockIdx.x * BN;
    const int co0 = blockIdx.y * BM;

    // ---- A load mapping: one (row, term) per thread ----
    const int arow  = tid & 127;
    const int aterm = tid >> 7;                 // 0 = hi, 1 = lo
    const uint32_t aswz = (uint32_t)(arow & 7) * 16;
    const __nv_bfloat16* awsrc = aterm ? g_w_lo : g_w_hi;
    const size_t wBase = (size_t)(co0 + arow) * KK;

    // ---- B load mapping: threads 0..127, one (row, term) each ----
    const int brow  = tid & 63;
    const int bterm = (tid >> 6) & 1;
    const uint32_t bswz = (uint32_t)(brow & 7) * 16;
    const int n  = n0 + brow;
    const int bb = n / NPIX;
    const int s  = n - bb * NPIX;
    const int py = s / W;
    const int px = s - py * W;
    const size_t pixBase = ((size_t)bb * NPIX + (size_t)py * W + px) * Cin;
    const __nv_bfloat16* binSrc = bterm ? g_in_lo : g_in_hi;

    // ---- per-lane ldmatrix constants ----
    const uint32_t aRowSel = (uint32_t)(lid & 15);
    const uint32_t aK16    = (uint32_t)(lid >> 4) * 16;
    const uint32_t swA     = (aRowSel & 7) * 16;
    const uint32_t bRowSel = (uint32_t)((lid & 7) + ((lid >> 4) & 1) * 8);
    const uint32_t bK16    = (uint32_t)((lid >> 3) & 1) * 16;
    const uint32_t swB     = (bRowSel & 7) * 16;

    float acc[4][2][4];
#pragma unroll
    for (int i = 0; i < 4; ++i)
#pragma unroll
        for (int j = 0; j < 2; ++j)
#pragma unroll
            for (int q = 0; q < 4; ++q) acc[i][j][q] = 0.0f;

    // ---- chunk load (cp.async, zero-fill for invalid taps) ----
    auto issue = [&](int c) {
        const uint32_t base = sb + (uint32_t)(c & 1) * STAGE;
        const int r    = c >> 1;
        const int cin0 = (c & 1) * 64;
        const int dy   = r / 3 - 1;
        const int dx   = r - (r / 3) * 3 - 1;

        // A: all 256 threads, one 128B row each
        {
            const __nv_bfloat16* src = awsrc + wBase + (size_t)c * KC;
            const uint32_t dst = base + (aterm ? OFF_ALO : OFF_AHI)
                               + (uint32_t)arow * 128;
#pragma unroll
            for (int j = 0; j < 8; ++j)
                cp16(dst + (((uint32_t)j * 16) ^ aswz), src + j * 8, 16);
        }
        // B: threads 0..127, one 128B row each
        if (tid < 128) {
            const bool valid = ((unsigned)(py + dy) < (unsigned)H) &&
                               ((unsigned)(px + dx) < (unsigned)W);
            const __nv_bfloat16* src = valid
                ? binSrc + pixBase + (ptrdiff_t)(dy * W + dx) * Cin + cin0
                : binSrc + pixBase;                // safe addr; 0 bytes read
            const uint32_t ssz = valid ? 16u : 0u;
            const uint32_t dst = base + (bterm ? OFF_BLO : OFF_BHI)
                               + (uint32_t)brow * 128;
#pragma unroll
            for (int j = 0; j < 8; ++j)
                cp16(dst + (((uint32_t)j * 16) ^ bswz), src + j * 8, ssz);
        }
    };

    issue(0);
    CP_COMMIT();

    for (int c = 0; c < NCHUNK; ++c) {
        if (c + 1 < NCHUNK) { issue(c + 1); CP_COMMIT(); CP_WAIT1(); }
        else                { CP_WAIT0(); }
        __syncthreads();

        const uint32_t base = sb + (uint32_t)(c & 1) * STAGE;
#pragma unroll
        for (int t = 0; t < 3; ++t) {       // 0: hh, 1: hi*lo(B), 2: lo(A)*hi
            const uint32_t aB = base + (t == 2 ? OFF_ALO : OFF_AHI);
            const uint32_t bB = base + (t == 1 ? OFF_BLO : OFF_BHI);
#pragma unroll
            for (int ks = 0; ks < 4; ++ks) {
                uint32_t a[4][4];
#pragma unroll
                for (int mf = 0; mf < 4; ++mf) {
                    uint32_t addr = aB
                        + (uint32_t)(warpM * 64 + mf * 16 + aRowSel) * 128
                        + (((uint32_t)ks * 32 + aK16) ^ swA);
                    LDSM_X4(a[mf][0], a[mf][1], a[mf][2], a[mf][3], addr);
                }
                uint32_t b[4];
                {
                    uint32_t addr = bB
                        + (uint32_t)(warpN * 16 + bRowSel) * 128
                        + (((uint32_t)ks * 32 + bK16) ^ swB);
                    LDSM_X4(b[0], b[1], b[2], b[3], addr);
                }
#pragma unroll
                for (int mf = 0; mf < 4; ++mf)
#pragma unroll
                    for (int nf = 0; nf < 2; ++nf)
                        MMA_BF16(acc[mf][nf], a[mf], b[nf * 2], b[nf * 2 + 1]);
            }
        }
        __syncthreads();
    }

    // ---- epilogue: bias + float2 stores ----
    const int rQuad = lid >> 2;
    const int cPair = (lid & 3) * 2;
#pragma unroll
    for (int mf = 0; mf < 4; ++mf) {
        const int coA = co0 + warpM * 64 + mf * 16 + rQuad;
        const int coB = coA + 8;
        const float bvA = __ldg(bias + coA);
        const float bvB = __ldg(bias + coB);
#pragma unroll
        for (int nf = 0; nf < 2; ++nf) {
            const int nn = n0 + warpN * 16 + nf * 8 + cPair;
            const int b2 = nn / NPIX;
            const int s2 = nn - b2 * NPIX;      // even; NPIX even -> no straddle
            float* po = out + ((size_t)b2 * Cout) * NPIX + s2;
            float2 vA, vB;
            vA.x = acc[mf][nf][0] + bvA;
            vA.y = acc[mf][nf][1] + bvA;
            vB.x = acc[mf][nf][2] + bvB;
            vB.y = acc[mf][nf][3] + bvB;
            *reinterpret_cast<float2*>(po + (size_t)coA * NPIX) = vA;
            *reinterpret_cast<float2*>(po + (size_t)coB * NPIX) = vB;
        }
    }
}

// ============================================================
// launch
// ============================================================
extern "C" void kernel_launch(void* const* d_in, const int* in_sizes, int n_in,
                              void* d_out, int out_size) {
    const float* tensor  = (const float*)d_in[0];
    const float* weights = (const float*)d_in[1];
    const float* bias    = (const float*)d_in[2];
    float* out           = (float*)d_out;

    prep_input_kernel<<<dim3(H, Bsz), 224>>>(tensor);
    prep_weights_kernel<<<(Cout * KK + 255) / 256, 256>>>(weights);

    cudaFuncSetAttribute(conv_mma_kernel,
                         cudaFuncAttributeMaxDynamicSharedMemorySize, SMEM_TOTAL);
    conv_mma_kernel<<<dim3(NTOT / BN, Cout / BM), 256, SMEM_TOTAL>>>(bias, out);
}

// round 17
// speedup vs baseline: 1.1189x; 1.1189x over previous
#include <cuda_runtime.h>
#include <cuda_bf16.h>
#include <cstdint>

// ============================================================
// OpticalConvolution: 3x3 conv pad1 NCHW fp32 as implicit GEMM
//   M=Cout=256, N=B*H*W=50176, K=Cin*9=1152
// bf16 3-term split (AhiBhi + AhiBlo + AloBhi) on mma.sync.
// R15: revert to BN=128 (best: 456.6us); share A-hi / B-hi
// fragments across split terms (18 -> 12 LDSM per ks);
// fuse prep kernels so ncu (-s 5 -c 1) captures conv_mma.
// ============================================================

constexpr int Cin  = 128;
constexpr int H    = 56;
constexpr int W    = 56;
constexpr int Cout = 256;
constexpr int Bsz  = 16;
constexpr int NPIX = H * W;          // 3136
constexpr int NTOT = Bsz * NPIX;     // 50176
constexpr int KK   = Cin * 9;        // 1152

constexpr int BM = 128;
constexpr int BN = 128;
constexpr int KC = 64;               // K per chunk (one tap, 64 cins)
constexpr int NCHUNK = KK / KC;      // 18

constexpr int TILE = BM * 128;       // 16384 B
constexpr int SMEM_TOTAL = 2 * 4 * TILE;   // 131072 B

// ---- device scratch ----
__device__ __align__(16) __nv_bfloat16 g_in_hi[(size_t)NTOT * Cin];
__device__ __align__(16) __nv_bfloat16 g_in_lo[(size_t)NTOT * Cin];
__device__ __align__(16) __nv_bfloat16 g_w_hi[Cout * KK];
__device__ __align__(16) __nv_bfloat16 g_w_lo[Cout * KK];

// ============================================================
// helpers
// ============================================================
__device__ __forceinline__ uint32_t smem_u32(const void* p) {
    uint32_t a;
    asm("{ .reg .u64 t; cvta.to.shared.u64 t, %1; cvt.u32.u64 %0, t; }"
        : "=r"(a) : "l"(p));
    return a;
}

__device__ __forceinline__ void cp16(uint32_t dst, const void* src, uint32_t srcsize) {
    asm volatile("cp.async.cg.shared.global [%0], [%1], 16, %2;"
                 :: "r"(dst), "l"(src), "r"(srcsize) : "memory");
}
#define CP_COMMIT() asm volatile("cp.async.commit_group;" ::: "memory")
#define CP_WAIT1()  asm volatile("cp.async.wait_group 1;" ::: "memory")
#define CP_WAIT0()  asm volatile("cp.async.wait_group 0;" ::: "memory")

#define LDSM_X4(r0, r1, r2, r3, addr) \
    asm volatile("ldmatrix.sync.aligned.m8n8.x4.shared.b16 {%0,%1,%2,%3}, [%4];" \
                 : "=r"(r0), "=r"(r1), "=r"(r2), "=r"(r3) : "r"(addr))

#define MMA_BF16(d, a, b0, b1) \
    asm volatile("mma.sync.aligned.m16n8k16.row.col.f32.bf16.bf16.f32 " \
                 "{%0,%1,%2,%3}, {%4,%5,%6,%7}, {%8,%9}, {%0,%1,%2,%3};" \
                 : "+f"((d)[0]), "+f"((d)[1]), "+f"((d)[2]), "+f"((d)[3]) \
                 : "r"((a)[0]), "r"((a)[1]), "r"((a)[2]), "r"((a)[3]), \
                   "r"(b0), "r"(b1))

// ============================================================
// Fused prep kernel: blocks [0,896) transpose/split the input,
// blocks [896, ...) split/reorder the weights.
// Fusion => 2 launches per replay => ncu -s 5 -c 1 captures conv.
// ============================================================
constexpr int PREP_IN_BLOCKS = H * Bsz;                       // 896
constexpr int W_ELEMS = Cout * KK;                            // 294912
constexpr int PREP_W_BLOCKS = (W_ELEMS + 223) / 224;          // 1317

__global__ __launch_bounds__(224)
void prep_fused_kernel(const float* __restrict__ in, const float* __restrict__ w) {
    __shared__ float stage[W][33];
    const int t = threadIdx.x;           // 0..223
    if (blockIdx.x < PREP_IN_BLOCKS) {
        const int b = blockIdx.x / H, y = blockIdx.x - b * H;
        const int xg = t % 56;
        const int cg = t / 56;           // 0..3
        for (int cin0 = 0; cin0 < Cin; cin0 += 32) {
#pragma unroll
            for (int j = 0; j < 8; ++j) {
                int cl = j * 4 + cg;
                stage[xg][cl] = in[((size_t)(b * Cin + cin0 + cl) * H + y) * W + xg];
            }
            __syncthreads();
#pragma unroll
            for (int j = 0; j < 8; ++j) {
                int o = t + 224 * j;      // 0..1791
                int cl = o & 31;
                int x  = o >> 5;
                float v = stage[x][cl];
                __nv_bfloat16 hi = __float2bfloat16(v);
                float lov = v - __bfloat162float(hi);
                size_t oi = ((size_t)b * NPIX + (size_t)y * W + x) * Cin + cin0 + cl;
                g_in_hi[oi] = hi;
                g_in_lo[oi] = __float2bfloat16(lov);
            }
            __syncthreads();
        }
    } else {
        int o = (blockIdx.x - PREP_IN_BLOCKS) * 224 + t;
        if (o < W_ELEMS) {
            int cout = o / KK;
            int k    = o - cout * KK;
            int r    = k >> 7;           // tap 0..8
            int cin  = k & 127;
            float v = w[((size_t)cout * Cin + cin) * 9 + r];
            __nv_bfloat16 hi = __float2bfloat16(v);
            g_w_hi[o] = hi;
            g_w_lo[o] = __float2bfloat16(v - __bfloat162float(hi));
        }
    }
}

// ============================================================
// Main mma.sync kernel: BM=128 x BN=128, fragment-shared terms
// ============================================================
__global__ __launch_bounds__(256, 1)
void conv_mma_kernel(const float* __restrict__ bias, float* __restrict__ out) {
    extern __shared__ char smem[];
    const uint32_t sb = smem_u32(smem);
    const int tid = threadIdx.x;
    const int wid = tid >> 5;
    const int lid = tid & 31;
    const int warpM = wid >> 2;       // 0..1  -> 64 cout rows
    const int warpN = wid & 3;        // 0..3  -> 32 pixel cols

    const int n0  = blockIdx.x * BN;
    const int co0 = blockIdx.y * BM;

    // ---- load mapping: 2 threads per tile-row; parity = hi/lo term ----
    const int lrow  = tid >> 1;       // 0..127
    const int lterm = tid & 1;        // 0 = hi, 1 = lo
    const uint32_t lsw = (uint32_t)(lrow & 7) * 16;

    const int n  = n0 + lrow;
    const int bb = n / NPIX;
    const int s  = n - bb * NPIX;
    const int py = s / W;
    const int px = s - py * W;
    const size_t pixBase = ((size_t)bb * NPIX + (size_t)py * W + px) * Cin;
    const __nv_bfloat16* binSrc = lterm ? g_in_lo : g_in_hi;
    const __nv_bfloat16* winSrc = lterm ? g_w_lo : g_w_hi;
    const size_t wBase = (size_t)(co0 + lrow) * KK;

    // ---- per-lane ldmatrix constants ----
    const uint32_t aRowSel = (uint32_t)(lid & 15);
    const uint32_t aK16    = (uint32_t)(lid >> 4) * 16;
    const uint32_t swA     = (aRowSel & 7) * 16;
    const uint32_t bRowSel = (uint32_t)((lid & 7) + ((lid >> 4) & 1) * 8);
    const uint32_t bK16    = (uint32_t)((lid >> 3) & 1) * 16;
    const uint32_t swB     = (bRowSel & 7) * 16;

    float acc[4][4][4];
#pragma unroll
    for (int i = 0; i < 4; ++i)
#pragma unroll
        for (int j = 0; j < 4; ++j)
#pragma unroll
            for (int q = 0; q < 4; ++q) acc[i][j][q] = 0.0f;

    // ---- chunk load (cp.async, zero-fill for invalid taps) ----
    auto issue = [&](int c) {
        const uint32_t base = sb + (uint32_t)(c & 1) * (4 * TILE);
        const uint32_t aT = base + (uint32_t)lterm * TILE;
        const uint32_t bT = base + 2 * TILE + (uint32_t)lterm * TILE;
        const int r    = c >> 1;
        const int cin0 = (c & 1) * 64;
        const int dy   = r / 3 - 1;
        const int dx   = r - (r / 3) * 3 - 1;

        const __nv_bfloat16* asrc = winSrc + wBase + (size_t)c * KC;
        const uint32_t aRowAddr = aT + (uint32_t)lrow * 128;
#pragma unroll
        for (int j = 0; j < 8; ++j)
            cp16(aRowAddr + (((uint32_t)j * 16) ^ lsw), asrc + j * 8, 16);

        const bool valid = ((unsigned)(py + dy) < (unsigned)H) &&
                           ((unsigned)(px + dx) < (unsigned)W);
        const __nv_bfloat16* bsrc = valid
            ? binSrc + pixBase + (ptrdiff_t)(dy * W + dx) * Cin + cin0
            : binSrc + pixBase;                    // safe addr; 0 bytes read
        const uint32_t ssz = valid ? 16u : 0u;
        const uint32_t bRowAddr = bT + (uint32_t)lrow * 128;
#pragma unroll
        for (int j = 0; j < 8; ++j)
            cp16(bRowAddr + (((uint32_t)j * 16) ^ lsw), bsrc + j * 8, ssz);
    };

    issue(0);
    CP_COMMIT();

    for (int c = 0; c < NCHUNK; ++c) {
        if (c + 1 < NCHUNK) { issue(c + 1); CP_COMMIT(); CP_WAIT1(); }
        else                { CP_WAIT0(); }
        __syncthreads();

        const uint32_t base = sb + (uint32_t)(c & 1) * (4 * TILE);
        const uint32_t aHiB = base;
        const uint32_t aLoB = base + TILE;
        const uint32_t bHiB = base + 2 * TILE;
        const uint32_t bLoB = base + 3 * TILE;

#pragma unroll
        for (int ks = 0; ks < 4; ++ks) {
            // ---- load all fragments once per ks (shared across terms) ----
            uint32_t aHi[4][4], aLo[4][4];
#pragma unroll
            for (int mf = 0; mf < 4; ++mf) {
                uint32_t rowOff = (uint32_t)(warpM * 64 + mf * 16 + aRowSel) * 128
                                + (((uint32_t)ks * 32 + aK16) ^ swA);
                LDSM_X4(aHi[mf][0], aHi[mf][1], aHi[mf][2], aHi[mf][3], aHiB + rowOff);
                LDSM_X4(aLo[mf][0], aLo[mf][1], aLo[mf][2], aLo[mf][3], aLoB + rowOff);
            }
            uint32_t bHi[2][4], bLo[2][4];
#pragma unroll
            for (int np = 0; np < 2; ++np) {
                uint32_t rowOff = (uint32_t)(warpN * 32 + np * 16 + bRowSel) * 128
                                + (((uint32_t)ks * 32 + bK16) ^ swB);
                LDSM_X4(bHi[np][0], bHi[np][1], bHi[np][2], bHi[np][3], bHiB + rowOff);
                LDSM_X4(bLo[np][0], bLo[np][1], bLo[np][2], bLo[np][3], bLoB + rowOff);
            }
            // ---- 3 split terms, 48 MMAs, no fragment reloads ----
#pragma unroll
            for (int mf = 0; mf < 4; ++mf)
#pragma unroll
                for (int nf = 0; nf < 4; ++nf)
                    MMA_BF16(acc[mf][nf], aHi[mf],
                             bHi[nf >> 1][(nf & 1) * 2], bHi[nf >> 1][(nf & 1) * 2 + 1]);
#pragma unroll
            for (int mf = 0; mf < 4; ++mf)
#pragma unroll
                for (int nf = 0; nf < 4; ++nf)
                    MMA_BF16(acc[mf][nf], aHi[mf],
                             bLo[nf >> 1][(nf & 1) * 2], bLo[nf >> 1][(nf & 1) * 2 + 1]);
#pragma unroll
            for (int mf = 0; mf < 4; ++mf)
#pragma unroll
                for (int nf = 0; nf < 4; ++nf)
                    MMA_BF16(acc[mf][nf], aLo[mf],
                             bHi[nf >> 1][(nf & 1) * 2], bHi[nf >> 1][(nf & 1) * 2 + 1]);
        }
        __syncthreads();
    }

    // ---- epilogue: bias + float2 stores ----
    const int rQuad = lid >> 2;
    const int cPair = (lid & 3) * 2;
#pragma unroll
    for (int mf = 0; mf < 4; ++mf) {
        const int coA = co0 + warpM * 64 + mf * 16 + rQuad;
        const int coB = coA + 8;
        const float bvA = __ldg(bias + coA);
        const float bvB = __ldg(bias + coB);
#pragma unroll
        for (int nf = 0; nf < 4; ++nf) {
            const int nn = n0 + warpN * 32 + nf * 8 + cPair;
            const int b2 = nn / NPIX;
            const int s2 = nn - b2 * NPIX;      // even; NPIX even -> no straddle
            float* po = out + ((size_t)b2 * Cout) * NPIX + s2;
            float2 vA, vB;
            vA.x = acc[mf][nf][0] + bvA;
            vA.y = acc[mf][nf][1] + bvA;
            vB.x = acc[mf][nf][2] + bvB;
            vB.y = acc[mf][nf][3] + bvB;
            *reinterpret_cast<float2*>(po + (size_t)coA * NPIX) = vA;
            *reinterpret_cast<float2*>(po + (size_t)coB * NPIX) = vB;
        }
    }
}

// ============================================================
// launch
// ============================================================
extern "C" void kernel_launch(void* const* d_in, const int* in_sizes, int n_in,
                              void* d_out, int out_size) {
    const float* tensor  = (const float*)d_in[0];
    const float* weights = (const float*)d_in[1];
    const float* bias    = (const float*)d_in[2];
    float* out           = (float*)d_out;

    prep_fused_kernel<<<PREP_IN_BLOCKS + PREP_W_BLOCKS, 224>>>(tensor, weights);

    cudaFuncSetAttribute(conv_mma_kernel,
                         cudaFuncAttributeMaxDynamicSharedMemorySize, SMEM_TOTAL);
    conv_mma_kernel<<<dim3(NTOT / BN, Cout / BM), 256, SMEM_TOTAL>>>(bias, out);
}